// round 5
// baseline (speedup 1.0000x reference)
#include <cuda_runtime.h>

typedef unsigned long long u64;

#define B  32
#define P  16384
#define O  16
#define NC 80
#define TOTAL4  (B * P * (NC / 4))    // 10,485,760 float4 of conf
#define NSTREAM 1184                  // streaming blocks (one wave); +1 patch block

// ---------------- device scratch (no allocations allowed) ----------------
__device__ float         g_overlap[B * P];   // pre-override best IoU (for patch)
__device__ int           g_bidx[B * P];      // pre-override best truth (for patch)
__device__ unsigned char g_valid[B * P];
__device__ u64           g_bestprior[B * O];
__device__ float         g_sum_ll;           // loc loss sum
__device__ float         g_sum_lcraw;        // sum of g0fast over valid elems (t=0 raw)
__device__ float         g_sum_corr;         // target-class corrections (true units)
__device__ int           g_poscnt;
__device__ int           g_done;             // block completion ticket

// ---------------- math helpers ----------------
__device__ __forceinline__ float frcp(float a) {
    float r; asm("rcp.approx.f32 %0, %1;" : "=f"(r) : "f"(a)); return r;
}

// A&S 4.1.43: ln(1+s) = s*(A1+s*(A2+s*(A3+s*(A4+s*A5)))), |err|<=1e-5 on [0,1]
#define LA1 0.99949556f
#define LA2 (-0.49190896f)
#define LA3 0.28947478f
#define LA4 (-0.13606275f)
#define LA5 0.03215845f

// fast g0(x) = softplus(x)*sigmoid(x): 2 MUFU (ex2, rcp), no divide, no log
__device__ __forceinline__ float g0fast_acc(float x, float acc) {
    float s = __expf(-fabsf(x));                     // exp(-|x|) in (0,1]
    float r = frcp(1.0f + s);
    float q = ((x >= 0.f) ? s : 1.0f) * r;           // sigmoid(-x)
    float L = s * fmaf(s, fmaf(s, fmaf(s, fmaf(s, LA5, LA4), LA3), LA2), LA1);
    float h = fmaxf(x, 0.f) + L;                     // softplus(x)
    return fmaf(h, -q, acc + h);                     // acc + h*(1-q)
}

__device__ __forceinline__ float g0raw(float x) {    // precise (cold paths)
    float e = __expf(-fabsf(x));
    float L = __logf(1.0f + e);
    float h = fmaxf(x, 0.0f) + L;
    float q = __expf(-h);
    return fmaf(-h, q, h);
}

__device__ __forceinline__ float bl1(float diff) {
    const float bb = 19.085537f;                     // e^3 - 1
    float d = fabsf(diff);
    if (d < 0.11f) {
        return (0.5f / bb) * (bb * d + 1.f) * log1pf(bb * d * (1.0f / 0.11f)) - 0.5f * d;
    }
    return 1.5f * d + (1.5f / bb - 0.5f * 0.11f);
}

// loc loss + focal target-class correction for a positive prior (b, truth j, prior p)
__device__ __forceinline__ void pos_meta(int b, int j, int p, int bp,
                                         const float4* __restrict__ priors,
                                         const float*  __restrict__ targets,
                                         const float*  __restrict__ conf,
                                         const float4* __restrict__ loc4,
                                         float& ll, float& corr) {
    const float* t = targets + (b * O + j) * 5;
    float m0 = t[0], m1 = t[1], m2 = t[2], m3 = t[3];
    int tc = (int)t[4] + 1;                          // 1..80
    float4 pp = priors[p];
    float ex = ((m0 + m2) * 0.5f - pp.x) / (0.1f * pp.z);
    float ey = ((m1 + m3) * 0.5f - pp.y) / (0.1f * pp.w);
    float ew = __logf((m2 - m0) / pp.z) * 5.0f;
    float eh = __logf((m3 - m1) / pp.w) * 5.0f;
    float4 ld = loc4[bp];
    ll = bl1(ld.x - ex) + bl1(ld.y - ey) + bl1(ld.z - ew) + bl1(ld.w - eh);
    float x = conf[bp * NC + (tc - 1)];
    corr = 0.25f * g0raw(-x) - 0.75f * g0raw(x);     // focal(x,1) - focal(x,0)
}

// ---------------- kernel 1: match + per-prior meta ----------------
// grid = (P/256, B), block = 256
__global__ void __launch_bounds__(256) k_match(const float4* __restrict__ priors,
                                               const float*  __restrict__ targets,
                                               const float*  __restrict__ conf,
                                               const float4* __restrict__ loc4) {
    __shared__ float4 s_tr[O];
    __shared__ float  s_area[O];
    __shared__ u64    s_key[O];

    int tid = threadIdx.x;
    int b   = blockIdx.y;
    int p   = blockIdx.x * blockDim.x + tid;

    if (tid < O) {
        const float* t = targets + (b * O + tid) * 5;
        float4 tr = make_float4(t[0], t[1], t[2], t[3]);   // already point-form
        s_tr[tid]   = tr;
        s_area[tid] = (tr.z - tr.x) * (tr.w - tr.y);
        s_key[tid]  = 0ull;
    }
    __syncthreads();

    float4 pr = priors[p];
    float px0 = pr.x - pr.z * 0.5f;
    float py0 = pr.y - pr.w * 0.5f;
    float px1 = pr.x + pr.z * 0.5f;
    float py1 = pr.y + pr.w * 0.5f;
    float areaB = (px1 - px0) * (py1 - py0);

    float best = -1.f;
    int   bidx = 0;
    #pragma unroll
    for (int j = 0; j < O; j++) {
        float4 tr = s_tr[j];
        float ix = fmaxf(fminf(tr.z, px1) - fmaxf(tr.x, px0), 0.f);
        float iy = fmaxf(fminf(tr.w, py1) - fmaxf(tr.y, py0), 0.f);
        float inter = ix * iy;
        float iou   = inter / (s_area[j] + areaB - inter);
        if (iou > best) { best = iou; bidx = j; }          // first-max (JAX argmax)
        u64 key = ((u64)__float_as_uint(iou) << 32) |
                  (unsigned)(0xFFFFFFFFu - (unsigned)p);   // ties -> smallest p
        if (key > s_key[j]) atomicMax(&s_key[j], key);
    }

    int bp = b * P + p;
    g_overlap[bp] = best;
    g_bidx[bp]    = bidx;

    bool pos   = best >= 0.5f;
    bool valid = pos || (best < 0.4f);
    g_valid[bp] = valid ? 1 : 0;

    float ll = 0.f, corr = 0.f;
    int pc = 0;
    if (pos) {
        pc = 1;
        pos_meta(b, bidx, p, bp, priors, targets, conf, loc4, ll, corr);
    }

    // block reduction of (ll, corr, pc)
    #pragma unroll
    for (int o = 16; o; o >>= 1) {
        ll   += __shfl_down_sync(0xFFFFFFFFu, ll, o);
        corr += __shfl_down_sync(0xFFFFFFFFu, corr, o);
        pc   += __shfl_down_sync(0xFFFFFFFFu, pc, o);
    }
    __shared__ float s_ll[8], s_co[8];
    __shared__ int   s_pc[8];
    int wid = tid >> 5, lane = tid & 31;
    if (lane == 0) { s_ll[wid] = ll; s_co[wid] = corr; s_pc[wid] = pc; }
    __syncthreads();
    if (wid == 0) {
        ll   = (lane < 8) ? s_ll[lane] : 0.f;
        corr = (lane < 8) ? s_co[lane] : 0.f;
        pc   = (lane < 8) ? s_pc[lane] : 0;
        #pragma unroll
        for (int o = 4; o; o >>= 1) {
            ll   += __shfl_down_sync(0xFFFFFFFFu, ll, o);
            corr += __shfl_down_sync(0xFFFFFFFFu, corr, o);
            pc   += __shfl_down_sync(0xFFFFFFFFu, pc, o);
        }
        if (lane == 0 && pc) {
            atomicAdd(&g_sum_ll, ll);
            atomicAdd(&g_sum_corr, corr);
            atomicAdd(&g_poscnt, pc);
        }
    }

    if (tid < O) {
        u64 key = s_key[tid];
        if (key > g_bestprior[b * O + tid]) atomicMax(&g_bestprior[b * O + tid], key);
    }
}

// ---------------- kernel 2: stream + patch block + last-block finalize ----------------
// grid = NSTREAM+1 blocks of 256. Blocks [0,NSTREAM) stream conf; block NSTREAM patches.
__global__ void __launch_bounds__(256) k_loss(const float4* __restrict__ conf4,
                                              const float4* __restrict__ priors,
                                              const float*  __restrict__ targets,
                                              const float*  __restrict__ conf,
                                              const float4* __restrict__ loc4,
                                              float* __restrict__ out) {
    int tid = threadIdx.x;
    int bid = blockIdx.x;

    if (bid < NSTREAM) {
        // ---- streaming focal (all valid rows as t=0) ----
        float lc0 = 0.f, lc1 = 0.f;
        int stride = NSTREAM * 256;
        for (int i = bid * 256 + tid; i < TOTAL4; i += stride) {
            unsigned bp = (unsigned)i / 20u;               // 20 float4 per prior
            if (g_valid[bp]) {
                float4 v = __ldcs(&conf4[i]);
                lc0 = g0fast_acc(v.x, lc0);
                lc1 = g0fast_acc(v.y, lc1);
                lc0 = g0fast_acc(v.z, lc0);
                lc1 = g0fast_acc(v.w, lc1);
            }
        }
        float lc = lc0 + lc1;
        #pragma unroll
        for (int o = 16; o; o >>= 1) lc += __shfl_down_sync(0xFFFFFFFFu, lc, o);
        __shared__ float s_a[8];
        int wid = tid >> 5, lane = tid & 31;
        if (lane == 0) s_a[wid] = lc;
        __syncthreads();
        if (wid == 0) {
            lc = (lane < 8) ? s_a[lane] : 0.f;
            #pragma unroll
            for (int o = 4; o; o >>= 1) lc += __shfl_down_sync(0xFFFFFFFFu, lc, o);
            if (lane == 0) atomicAdd(&g_sum_lcraw, lc);
        }
    } else {
        // ---- patch block: force-match deltas (runs concurrently with streaming) ----
        __shared__ unsigned s_p[B * O];
        // load 512 best-prior results with 256 threads
        for (int e = tid; e < B * O; e += 256) {
            u64 key = g_bestprior[e];
            s_p[e] = 0xFFFFFFFFu - (unsigned)(key & 0xFFFFFFFFull);
            g_bestprior[e] = 0ull;                         // reset for next replay
        }
        __syncthreads();

        for (int e = tid; e < B * O; e += 256) {
            int b = e >> 4, j = e & 15;
            unsigned p = s_p[e];
            bool apply = true;                             // last truth targeting p wins
            for (int j2 = j + 1; j2 < O; j2++)
                if (s_p[(b << 4) | j2] == p) { apply = false; break; }
            if (!apply) continue;

            int bp = b * P + (int)p;
            float oldov    = g_overlap[bp];
            int   oldj     = g_bidx[bp];
            bool  oldpos   = oldov >= 0.5f;
            bool  oldvalid = oldpos || (oldov < 0.4f);

            float ll_n, corr_n;
            pos_meta(b, j, (int)p, bp, priors, targets, conf, loc4, ll_n, corr_n);
            float dll = ll_n, dcorr = corr_n;
            if (oldpos) {                                  // remove k_match's contribution
                float ll_o, corr_o;
                pos_meta(b, oldj, (int)p, bp, priors, targets, conf, loc4, ll_o, corr_o);
                dll -= ll_o; dcorr -= corr_o;
            } else {
                atomicAdd(&g_poscnt, 1);
            }
            if (!oldvalid) {                               // row skipped in base stream
                const float* row = conf + (long)bp * NC;
                float s = 0.f;
                #pragma unroll 4
                for (int c = 0; c < NC; c++) s = g0fast_acc(row[c], s);
                atomicAdd(&g_sum_lcraw, s);
            }
            atomicAdd(&g_sum_ll, dll);
            atomicAdd(&g_sum_corr, dcorr);
        }
        __syncthreads();
    }

    // ---- completion ticket; last block finalizes + resets ----
    if (tid == 0) {
        __threadfence();
        int t = atomicAdd(&g_done, 1);
        if (t == NSTREAM) {                                // last of NSTREAM+1 blocks
            float pn = fmaxf((float)g_poscnt, 1.0f);
            out[0] = g_sum_ll / (pn * 4.0f);
            out[1] = (0.75f * g_sum_lcraw + g_sum_corr) / pn;
            g_sum_ll = 0.f; g_sum_lcraw = 0.f; g_sum_corr = 0.f;
            g_poscnt = 0; g_done = 0;
        }
    }
}

// ---------------- launch ----------------
extern "C" void kernel_launch(void* const* d_in, const int* in_sizes, int n_in,
                              void* d_out, int out_size) {
    const float4* loc4    = (const float4*)d_in[0];   // (B,P,4)  f32
    const float4* conf4   = (const float4*)d_in[1];   // (B,P,80) f32
    const float*  conf    = (const float*)d_in[1];
    const float4* priors4 = (const float4*)d_in[2];   // (P,4)    f32
    const float*  targets = (const float*)d_in[3];    // (B,O,5)  f32
    float* out = (float*)d_out;

    dim3 mg(P / 256, B);                              // 2048 blocks
    k_match<<<mg, 256>>>(priors4, targets, conf, loc4);
    k_loss<<<NSTREAM + 1, 256>>>(conf4, priors4, targets, conf, loc4, out);
}